// round 14
// baseline (speedup 1.0000x reference)
#include <cuda_runtime.h>
#include <cuda_fp16.h>
#include <mma.h>

using namespace nvcuda;

#define B_  2
#define T_  2048
#define M_  2048
#define C_  1024
#define H_  16
#define TK_ 4096
#define CSL 0.18033688011112042f   // 0.125 * log2(e)

// ---------------- scratch (device globals, all fp16) ------------------------
__device__ __half g_q  [B_*T_ *C_];
__device__ __half g_k  [B_*TK_*C_];
__device__ __half g_v  [B_*TK_*C_];
__device__ __half g_wv [B_*T_ *C_];
__device__ __half g_xh [B_*T_ *C_];
__device__ __half g_wq [C_*C_];
__device__ __half g_wk [C_*C_];
__device__ __half g_wvw[C_*C_];
__device__ __half g_wp [C_*C_];

// ---------------- helpers ---------------------------------------------------
__device__ __forceinline__ void cp16(void* dst, const void* src) {
    unsigned sdst = (unsigned)__cvta_generic_to_shared(dst);
    asm volatile("cp.async.cg.shared.global [%0], [%1], 16;\n" :: "r"(sdst), "l"(src));
}
#define CP_COMMIT() asm volatile("cp.async.commit_group;\n")
#define CP_WAIT0()  asm volatile("cp.async.wait_group 0;\n")
#define CP_WAIT1()  asm volatile("cp.async.wait_group 1;\n")
#define CP_WAIT2()  asm volatile("cp.async.wait_group 2;\n")
#define CP_WAIT3()  asm volatile("cp.async.wait_group 3;\n")

// ---------------- fused prep ------------------------------------------------
#define NX4 (B_*T_*C_/4)
#define NW4 (C_*C_/4)
#define NXL4 (B_*M_*C_/4)
#define NPREP (NX4 + 4*NW4 + NXL4)
__global__ void prep_kernel(const float4* __restrict__ x,
                            const float4* __restrict__ Wq,
                            const float4* __restrict__ Wk,
                            const float4* __restrict__ Wv,
                            const float4* __restrict__ Wp,
                            const float4* __restrict__ xl) {
    int i = blockIdx.x * blockDim.x + threadIdx.x;
    if (i >= NPREP) return;
    if (i < NX4 + 4*NW4) {
        const float4* src;
        __half* dst;
        float s = 1.0f;
        if (i < NX4) {
            src = x + i; dst = g_xh + (size_t)i*4;
        } else {
            int j = i - NX4;
            int reg = j >> 18;
            int off = j & (NW4 - 1);
            if (reg == 0)      { src = Wq + off; dst = g_wq  + (size_t)off*4; s = CSL; }
            else if (reg == 1) { src = Wk + off; dst = g_wk  + (size_t)off*4; }
            else if (reg == 2) { src = Wv + off; dst = g_wvw + (size_t)off*4; }
            else               { src = Wp + off; dst = g_wp  + (size_t)off*4; }
        }
        float4 a = *src;
        __half2* d2 = (__half2*)dst;
        d2[0] = __floats2half2_rn(a.x * s, a.y * s);
        d2[1] = __floats2half2_rn(a.z * s, a.w * s);
    } else {
        int idx = i - (NX4 + 4*NW4);
        int c4 = idx % (C_/4);
        int bm = idx / (C_/4);
        int m  = bm % M_;
        int b  = bm / M_;
        float4 kk = xl[((size_t)(b*M_ + m)*2 + 0)*(C_/4) + c4];
        float4 vv = xl[((size_t)(b*M_ + m)*2 + 1)*(C_/4) + c4];
        __half2* kp = (__half2*)(g_k + (size_t)(b*TK_ + m)*C_ + c4*4);
        __half2* vp = (__half2*)(g_v + (size_t)(b*TK_ + m)*C_ + c4*4);
        kp[0] = __floats2half2_rn(kk.x, kk.y); kp[1] = __floats2half2_rn(kk.z, kk.w);
        vp[0] = __floats2half2_rn(vv.x, vv.y); vp[1] = __floats2half2_rn(vv.z, vv.w);
    }
}

// ---------------- projection GEMMs (fp16, 128x128, k-chunk 64) --------------
#define PLDA 72    // halves (64 + 8 pad)
#define PLDB 136   // halves
#define PLDC 136   // floats
#define PROJ_SMEM_BYTES ((2*128*PLDA + 2*64*PLDB)*2)   // 71680; Cs (69632) aliases

struct ProjAcc {
    wmma::fragment<wmma::accumulator,16,16,16,float> acc[2][4];
};

__device__ __forceinline__ void proj_issue(__half* As, __half* Bs, int buf,
                                           const __half* A, const __half* W,
                                           int row0, int wcol0, int kc, int tid) {
    #pragma unroll
    for (int ch = tid; ch < 1024; ch += 256) {
        int r = ch >> 3, s = ch & 7;   // 128 rows x 8 chunks (64 halves)
        cp16(&As[(size_t)buf*128*PLDA + r*PLDA + s*8], A + (size_t)(row0 + r)*C_ + kc*64 + s*8);
    }
    #pragma unroll
    for (int ch = tid; ch < 1024; ch += 256) {
        int r = ch >> 4, s = ch & 15;  // 64 rows x 16 chunks (128 halves)
        cp16(&Bs[(size_t)buf*64*PLDB + r*PLDB + s*8], W + (size_t)(kc*64 + r)*C_ + wcol0 + s*8);
    }
    CP_COMMIT();
}

__device__ __forceinline__ void proj_mainloop(float* sm, const __half* A, const __half* W,
                                              int row0, int wcol0, ProjAcc& P) {
    __half* As = (__half*)sm;
    __half* Bs = (__half*)sm + 2*128*PLDA;
    int tid = threadIdx.x, warp = tid >> 5;
    int wr = warp >> 1, wc = warp & 1;

    #pragma unroll
    for (int i = 0; i < 2; i++)
        #pragma unroll
        for (int j = 0; j < 4; j++) wmma::fill_fragment(P.acc[i][j], 0.0f);

    proj_issue(As, Bs, 0, A, W, row0, wcol0, 0, tid);
    for (int kc = 0; kc < 16; kc++) {
        int buf = kc & 1;
        CP_WAIT0();
        __syncthreads();
        if (kc + 1 < 16) proj_issue(As, Bs, buf ^ 1, A, W, row0, wcol0, kc + 1, tid);
        __half* Ab = &As[(size_t)buf*128*PLDA];
        __half* Bb = &Bs[(size_t)buf*64*PLDB];
        #pragma unroll
        for (int ks = 0; ks < 4; ks++) {
            wmma::fragment<wmma::matrix_a,16,16,16,__half,wmma::row_major> a0, a1;
            wmma::load_matrix_sync(a0, &Ab[(wr*32     )*PLDA + ks*16], PLDA);
            wmma::load_matrix_sync(a1, &Ab[(wr*32 + 16)*PLDA + ks*16], PLDA);
            #pragma unroll
            for (int j = 0; j < 4; j++) {
                wmma::fragment<wmma::matrix_b,16,16,16,__half,wmma::row_major> b;
                wmma::load_matrix_sync(b, &Bb[(ks*16)*PLDB + wc*64 + j*16], PLDB);
                wmma::mma_sync(P.acc[0][j], a0, b, P.acc[0][j]);
                wmma::mma_sync(P.acc[1][j], a1, b, P.acc[1][j]);
            }
        }
    }
    __syncthreads();
    float* Cs = sm;
    #pragma unroll
    for (int i = 0; i < 2; i++)
        #pragma unroll
        for (int j = 0; j < 4; j++)
            wmma::store_matrix_sync(&Cs[(wr*32 + i*16)*PLDC + wc*64 + j*16],
                                    P.acc[i][j], PLDC, wmma::mem_row_major);
    __syncthreads();
}

__global__ __launch_bounds__(256, 2) void proj_qkv_kernel(float* __restrict__ out_xl) {
    extern __shared__ __align__(16) float sm[];
    int col0 = blockIdx.x * 128;
    int row0 = blockIdx.y * 128;
    int wsel  = col0 >> 10;
    int wcol0 = col0 & 1023;
    const __half* W = (wsel == 0) ? g_wq : ((wsel == 1) ? g_wk : g_wvw);

    ProjAcc P;
    proj_mainloop(sm, g_xh, W, row0, wcol0, P);

    float* Cs = sm;
    int tid = threadIdx.x;
    for (int i = tid; i < 128*64; i += 256) {
        int r = i >> 6, c2 = (i & 63) * 2;
        float v0 = Cs[r*PLDC + c2];
        float v1 = Cs[r*PLDC + c2 + 1];
        int row = row0 + r;
        int b = row >> 11, t = row & 2047;
        int cc = wcol0 + c2;
        __half2 hv = __floats2half2_rn(v0, v1);
        if (wsel == 0) {
            *(__half2*)(g_q + (size_t)row*C_ + cc) = hv;
        } else if (wsel == 1) {
            *(__half2*)(g_k + ((size_t)b*TK_ + M_ + t)*C_ + cc) = hv;
            *(float2*)(out_xl + (((size_t)(b*T_ + t))*2 + 0)*C_ + cc) = make_float2(v0, v1);
        } else {
            *(__half2*)(g_v + ((size_t)b*TK_ + M_ + t)*C_ + cc) = hv;
            *(float2*)(out_xl + (((size_t)(b*T_ + t))*2 + 1)*C_ + cc) = make_float2(v0, v1);
        }
    }
}

__global__ __launch_bounds__(256, 2) void proj_out_kernel(const float* __restrict__ bp,
                                                          float* __restrict__ out) {
    extern __shared__ __align__(16) float sm[];
    int col0 = blockIdx.x * 128;
    int row0 = blockIdx.y * 128;

    ProjAcc P;
    proj_mainloop(sm, g_wv, g_wp, row0, col0, P);

    float* Cs = sm;
    int tid = threadIdx.x;
    for (int i = tid; i < 128*64; i += 256) {
        int r = i >> 6, c2 = (i & 63) * 2;
        float2 v = make_float2(Cs[r*PLDC + c2]     + bp[col0 + c2],
                               Cs[r*PLDC + c2 + 1] + bp[col0 + c2 + 1]);
        *(float2*)(out + (size_t)(row0 + r)*C_ + col0 + c2) = v;
    }
}

// ---------------- flash attention (R11/R13 + 4-deep K/V ring) ----------------
#define LDH 72
#define NSTAGE 4
#define AK_OFF (128*LDH)
#define AV_OFF (AK_OFF + NSTAGE*64*LDH)
#define ATTN_SMEM_BYTES ((128*LDH + 2*NSTAGE*64*LDH)*2)   // 92160; x2 CTAs = 184320

#define MMA_F16(C0,C1,C2,C3,A0,A1,A2,A3,Bb0,Bb1)                               \
    asm volatile("mma.sync.aligned.m16n8k16.row.col.f32.f16.f16.f32 "          \
                 "{%0,%1,%2,%3},{%4,%5,%6,%7},{%8,%9},{%0,%1,%2,%3};"          \
                 : "+f"(C0), "+f"(C1), "+f"(C2), "+f"(C3)                      \
                 : "r"(A0), "r"(A1), "r"(A2), "r"(A3), "r"(Bb0), "r"(Bb1))

__global__ __launch_bounds__(128, 2) void attn_kernel(const float* __restrict__ rel) {
    extern __shared__ __align__(16) __half smh[];
    __half* Qs = smh;
    __half* Ks = smh + AK_OFF;
    __half* Vs = smh + AV_OFF;

    int bx = blockIdx.x;
    int b  = bx & 1;
    int qt = 15 - (bx >> 1);
    int h  = blockIdx.y;
    int qi0 = qt * 128;
    int tid = threadIdx.x, warp = tid >> 5, lane = tid & 31;
    int g  = lane >> 2;
    int t4 = lane & 3;

    const __half* kbase = g_k + (size_t)b*TK_*C_ + h*64;
    const __half* vbase = g_v + (size_t)b*TK_*C_ + h*64;
    const __half* qbase = g_q + ((size_t)b*T_ + qi0)*C_ + h*64;
    const float*  relb  = rel + (size_t)h*T_*TK_;

    int ntiles = 2*qt + 34;

    // ---- prologue: Q, then tiles 0,1,2 ----
    for (int ch = tid; ch < 1024; ch += 128) {
        int r = ch >> 3, s = ch & 7;
        cp16(&Qs[r*LDH + s*8], qbase + (size_t)r*C_ + s*8);
    }
    CP_COMMIT();
    #pragma unroll
    for (int pre = 0; pre < 3; pre++) {
        for (int ch = tid; ch < 1024; ch += 128) {
            if (ch < 512) {
                int r = ch >> 3, s = ch & 7;
                cp16(&Ks[pre*64*LDH + r*LDH + s*8], kbase + (size_t)(pre*64 + r)*C_ + s*8);
            } else {
                int c2 = ch - 512;
                int r = c2 >> 3, s = c2 & 7;
                cp16(&Vs[pre*64*LDH + r*LDH + s*8], vbase + (size_t)(pre*64 + r)*C_ + s*8);
            }
        }
        CP_COMMIT();
    }

    // V padding cols 64..71 (ones column at 64) for all NSTAGE ring buffers
    for (int i = tid; i < NSTAGE*64; i += 128) {
        __half2* pad = (__half2*)(Vs + (size_t)i*LDH + 64);
        pad[0] = __floats2half2_rn(1.0f, 0.0f);
        pad[1] = __floats2half2_rn(0.0f, 0.0f);
        pad[2] = __floats2half2_rn(0.0f, 0.0f);
        pad[3] = __floats2half2_rn(0.0f, 0.0f);
    }

    CP_WAIT3();                          // Q staged; 3 tiles may be in flight
    __syncthreads();

    int lm   = lane & 15;
    int lmc  = (lane >> 4) * 8;
    int lmrt = ((lane >> 3) & 1) * 8 + (lane & 7);
    int lmct = (lane >> 4) * 8;
    unsigned qsm  = (unsigned)__cvta_generic_to_shared(Qs);
    unsigned ksm0 = (unsigned)__cvta_generic_to_shared(Ks);
    unsigned vsm0 = (unsigned)__cvta_generic_to_shared(Vs);

    unsigned qa[2][4][4];
    #pragma unroll
    for (int s = 0; s < 2; s++)
        #pragma unroll
        for (int kk = 0; kk < 4; kk++) {
            unsigned addr = qsm + (unsigned)(((warp*32 + s*16 + lm)*LDH + kk*16 + lmc) * 2);
            asm volatile("ldmatrix.sync.aligned.m8n8.x4.shared.b16 {%0,%1,%2,%3}, [%4];"
                         : "=r"(qa[s][kk][0]), "=r"(qa[s][kk][1]),
                           "=r"(qa[s][kk][2]), "=r"(qa[s][kk][3])
                         : "r"(addr));
        }

    float o[2][8][4];
    float oE[2][4];
    #pragma unroll
    for (int s = 0; s < 2; s++) {
        #pragma unroll
        for (int n = 0; n < 8; n++)
            #pragma unroll
            for (int j = 0; j < 4; j++) o[s][n][j] = 0.0f;
        #pragma unroll
        for (int j = 0; j < 4; j++) oE[s][j] = 0.0f;
    }

    for (int kt = 0; kt < ntiles; kt++) {
        int buf = kt & (NSTAGE - 1);
        int kj0 = kt * 64;

        // strip-0 bias prefetch (overlaps pipeline wait + QK)
        int row0s = qi0 + warp*32 + g;
        float2 rv0[16];
        {
            const float2* rl = (const float2*)(relb + (size_t)row0s*TK_ + kj0);
            const float2* rh = (const float2*)(relb + (size_t)(row0s + 8)*TK_ + kj0);
            #pragma unroll
            for (int n = 0; n < 8; n++) {
                rv0[n]     = __ldg(rl + 4*n + t4);
                rv0[8 + n] = __ldg(rh + 4*n + t4);
            }
        }

        CP_WAIT2();                       // tile kt complete (<=2 younger in flight)
        __syncthreads();
        if (kt + 3 < ntiles) {
            int tt = kt + 3, nb = tt & (NSTAGE - 1);
            for (int ch = tid; ch < 1024; ch += 128) {
                if (ch < 512) {
                    int r = ch >> 3, s = ch & 7;
                    cp16(&Ks[nb*64*LDH + r*LDH + s*8], kbase + (size_t)(tt*64 + r)*C_ + s*8);
                } else {
                    int c2 = ch - 512;
                    int r = c2 >> 3, s = c2 & 7;
                    cp16(&Vs[nb*64*LDH + r*LDH + s*8], vbase + (size_t)(tt*64 + r)*C_ + s*8);
                }
            }
            CP_COMMIT();
        }
        unsigned ksm = ksm0 + (unsigned)(buf * 64 * LDH * 2);
        unsigned vsm = vsm0 + (unsigned)(buf * 64 * LDH * 2);

        // ---- S = Q @ K^T, both strips, K frags read once per warp ----
        float accS[2][8][4];
        #pragma unroll
        for (int s = 0; s < 2; s++)
            #pragma unroll
            for (int n = 0; n < 8; n++)
                #pragma unroll
                for (int j = 0; j < 4; j++) accS[s][n][j] = 0.0f;
        #pragma unroll
        for (int kk = 0; kk < 4; kk++) {
            #pragma unroll
            for (int np = 0; np < 4; np++) {
                unsigned addr = ksm + (unsigned)(((16*np + lm)*LDH + kk*16 + lmc) * 2);
                unsigned r0, r1, r2, r3;
                asm volatile("ldmatrix.sync.aligned.m8n8.x4.shared.b16 {%0,%1,%2,%3}, [%4];"
                             : "=r"(r0), "=r"(r1), "=r"(r2), "=r"(r3) : "r"(addr));
                #pragma unroll
                for (int s = 0; s < 2; s++) {
                    MMA_F16(accS[s][2*np][0], accS[s][2*np][1], accS[s][2*np][2], accS[s][2*np][3],
                            qa[s][kk][0], qa[s][kk][1], qa[s][kk][2], qa[s][kk][3], r0, r2);
                    MMA_F16(accS[s][2*np+1][0], accS[s][2*np+1][1], accS[s][2*np+1][2], accS[s][2*np+1][3],
                            qa[s][kk][0], qa[s][kk][1], qa[s][kk][2], qa[s][kk][3], r1, r3);
                }
            }
        }

        // strip-1 bias (prefetched before softmax, overlapping)
        float2 rv1[16];
        {
            int row1s = row0s + 16;
            const float2* rl = (const float2*)(relb + (size_t)row1s*TK_ + kj0);
            const float2* rh = (const float2*)(relb + (size_t)(row1s + 8)*TK_ + kj0);
            #pragma unroll
            for (int n = 0; n < 8; n++) {
                rv1[n]     = __ldg(rl + 4*n + t4);
                rv1[8 + n] = __ldg(rh + 4*n + t4);
            }
        }

        bool masked = (kt >= ntiles - 2);

        // ---- softmax both strips: fp32 logit -> f16x2 pack -> ex2.f16x2 ----
        unsigned pg[2][8], ph[2][8];
        #pragma unroll
        for (int s = 0; s < 2; s++) {
            float2* rv = (s == 0) ? rv0 : rv1;
            int rowbase = row0s + s*16;
            int lim_lo = rowbase + 2048 - kj0;
            int lim_hi = lim_lo + 8;
            #pragma unroll
            for (int n = 0; n < 8; n++) {
                int cbase = 8*n + 2*t4;
                float p0 = fmaf(rv[n].x,     CSL, accS[s][n][0]);
                float p1 = fmaf(rv[n].y,     CSL, accS[s][n][1]);
                float q0 = fmaf(rv[8 + n].x, CSL, accS[s][n][2]);
                float q1 = fmaf(rv[8 + n].y, CSL, accS[s][n][3]);
                if (masked) {
                    if (cbase     > lim_lo) p0 = -100000.0f;
                    if (cbase + 1 > lim_lo) p1 = -100000.0f;
                    if (cbase     > lim_hi) q0 = -100000.0f;
                    if (cbase + 1 > lim_hi) q1 = -100000.0f;
                }
                unsigned u0, u1;
                asm("cvt.rn.f16x2.f32 %0, %1, %2;" : "=r"(u0) : "f"(p1), "f"(p0));
                asm("ex2.approx.f16x2 %0, %1;"     : "=r"(pg[s][n]) : "r"(u0));
                asm("cvt.rn.f16x2.f32 %0, %1, %2;" : "=r"(u1) : "f"(q1), "f"(q0));
                asm("ex2.approx.f16x2 %0, %1;"     : "=r"(ph[s][n]) : "r"(u1));
            }
        }

        // ---- PV: one V-fragment load serves both strips; ones-col -> sums ----
        #pragma unroll
        for (int kk = 0; kk < 4; kk++) {
            unsigned a00 = pg[0][2*kk], a01 = ph[0][2*kk];
            unsigned a02 = pg[0][2*kk+1], a03 = ph[0][2*kk+1];
            unsigned a10 = pg[1][2*kk], a11 = ph[1][2*kk];
            unsigned a12 = pg[1][2*kk+1], a13 = ph[1][2*kk+1];
            #pragma unroll
            for (int jv = 0; jv < 4; jv++) {
                unsigned baddr = vsm + (unsigned)(((16*kk + lmrt)*LDH + 16*jv + lmct) * 2);
                unsigned b0, b1, b2, b3;
                asm volatile("ldmatrix.sync.aligned.m8n8.x4.trans.shared.b16 "
                             "{%0,%1,%2,%3}, [%4];"
                             : "=r"(b0), "=r"(b1), "=r"(b2), "=r"(b3) : "r"(baddr));
                MMA_F16(o[0][2*jv][0], o[0][2*jv][1], o[0][2*jv][2], o[0][2*jv][3],
                        a00, a01, a02, a03, b0, b1);
                MMA_F16(o[0][2*jv+1][0], o[0][2*jv+1][1], o[0][2*jv+1][2], o[0][2*jv+1][3],
                        a00, a01, a02, a03, b2, b3);
                MMA_F16(o[1][2*jv][0], o[1][2*jv][1], o[1][2*jv][2], o[1][2*jv][3],
                        a10, a11, a12, a13, b0, b1);
                MMA_F16(o[1][2*jv+1][0], o[1][2*jv+1][1], o[1][2*jv+1][2], o[1][2*jv+1][3],
                        a10, a11, a12, a13, b2, b3);
            }
            unsigned caddr = vsm + (unsigned)(((16*kk + (lane & 15))*LDH + 64) * 2);
            unsigned c0, c1;
            asm volatile("ldmatrix.sync.aligned.m8n8.x2.trans.shared.b16 {%0,%1}, [%2];"
                         : "=r"(c0), "=r"(c1) : "r"(caddr));
            MMA_F16(oE[0][0], oE[0][1], oE[0][2], oE[0][3], a00, a01, a02, a03, c0, c1);
            MMA_F16(oE[1][0], oE[1][1], oE[1][2], oE[1][3], a10, a11, a12, a13, c0, c1);
        }
    }

    // ---- normalize + write ----
    #pragma unroll
    for (int s = 0; s < 2; s++) {
        float sum_lo = __shfl_sync(0xFFFFFFFFu, oE[s][0], lane & 28);
        float sum_hi = __shfl_sync(0xFFFFFFFFu, oE[s][2], lane & 28);
        float inv_lo = 1.0f / sum_lo;
        float inv_hi = 1.0f / sum_hi;
        int rowbase = warp*32 + s*16 + g;
        __half* wv_lo = g_wv + ((size_t)b*T_ + qi0 + rowbase    )*C_ + h*64 + 2*t4;
        __half* wv_hi = g_wv + ((size_t)b*T_ + qi0 + rowbase + 8)*C_ + h*64 + 2*t4;
        #pragma unroll
        for (int n = 0; n < 8; n++) {
            *(__half2*)(wv_lo + 8*n) = __floats2half2_rn(o[s][n][0]*inv_lo, o[s][n][1]*inv_lo);
            *(__half2*)(wv_hi + 8*n) = __floats2half2_rn(o[s][n][2]*inv_hi, o[s][n][3]*inv_hi);
        }
    }
}

// ---------------- launch ----------------------------------------------------
extern "C" void kernel_launch(void* const* d_in, const int* in_sizes, int n_in,
                              void* d_out, int out_size) {
    const float* rel = (const float*)d_in[0];
    const float* x   = (const float*)d_in[1];
    const float* xl  = (const float*)d_in[2];
    const float* Wq  = (const float*)d_in[3];
    const float* Wk  = (const float*)d_in[4];
    const float* Wv  = (const float*)d_in[5];
    const float* Wp  = (const float*)d_in[6];
    const float* bp  = (const float*)d_in[7];

    float* out    = (float*)d_out;
    float* out_xl = out + (size_t)B_*T_*C_;

    cudaFuncSetAttribute(proj_qkv_kernel, cudaFuncAttributeMaxDynamicSharedMemorySize, PROJ_SMEM_BYTES);
    cudaFuncSetAttribute(proj_out_kernel, cudaFuncAttributeMaxDynamicSharedMemorySize, PROJ_SMEM_BYTES);
    cudaFuncSetAttribute(attn_kernel,     cudaFuncAttributeMaxDynamicSharedMemorySize, ATTN_SMEM_BYTES);

    prep_kernel<<<(NPREP + 255)/256, 256>>>((const float4*)x,  (const float4*)Wq,
                                            (const float4*)Wk, (const float4*)Wv,
                                            (const float4*)Wp, (const float4*)xl);

    proj_qkv_kernel<<<dim3(24, 32), 256, PROJ_SMEM_BYTES>>>(out_xl);
    attn_kernel<<<dim3(32, 16), 128, ATTN_SMEM_BYTES>>>(rel);
    proj_out_kernel<<<dim3(8, 32), 256, PROJ_SMEM_BYTES>>>(bp, out);
}

// round 15
// speedup vs baseline: 1.0293x; 1.0293x over previous
#include <cuda_runtime.h>
#include <cuda_fp16.h>
#include <mma.h>

using namespace nvcuda;

#define B_  2
#define T_  2048
#define M_  2048
#define C_  1024
#define H_  16
#define TK_ 4096
#define CSL 0.18033688011112042f   // 0.125 * log2(e)

// ---------------- scratch (device globals, all fp16) ------------------------
__device__ __half g_q  [B_*T_ *C_];
__device__ __half g_k  [B_*TK_*C_];
__device__ __half g_v  [B_*TK_*C_];
__device__ __half g_wv [B_*T_ *C_];
__device__ __half g_xh [B_*T_ *C_];
__device__ __half g_wq [C_*C_];
__device__ __half g_wk [C_*C_];
__device__ __half g_wvw[C_*C_];
__device__ __half g_wp [C_*C_];

// ---------------- helpers ---------------------------------------------------
__device__ __forceinline__ void cp16(void* dst, const void* src) {
    unsigned sdst = (unsigned)__cvta_generic_to_shared(dst);
    asm volatile("cp.async.cg.shared.global [%0], [%1], 16;\n" :: "r"(sdst), "l"(src));
}
#define CP_COMMIT() asm volatile("cp.async.commit_group;\n")
#define CP_WAIT0()  asm volatile("cp.async.wait_group 0;\n")
#define CP_WAIT1()  asm volatile("cp.async.wait_group 1;\n")
#define CP_WAIT2()  asm volatile("cp.async.wait_group 2;\n")

// ---------------- fused prep ------------------------------------------------
#define NX4 (B_*T_*C_/4)
#define NW4 (C_*C_/4)
#define NXL4 (B_*M_*C_/4)
#define NPREP (NX4 + 4*NW4 + NXL4)
__global__ void prep_kernel(const float4* __restrict__ x,
                            const float4* __restrict__ Wq,
                            const float4* __restrict__ Wk,
                            const float4* __restrict__ Wv,
                            const float4* __restrict__ Wp,
                            const float4* __restrict__ xl) {
    int i = blockIdx.x * blockDim.x + threadIdx.x;
    if (i >= NPREP) return;
    if (i < NX4 + 4*NW4) {
        const float4* src;
        __half* dst;
        float s = 1.0f;
        if (i < NX4) {
            src = x + i; dst = g_xh + (size_t)i*4;
        } else {
            int j = i - NX4;
            int reg = j >> 18;
            int off = j & (NW4 - 1);
            if (reg == 0)      { src = Wq + off; dst = g_wq  + (size_t)off*4; s = CSL; }
            else if (reg == 1) { src = Wk + off; dst = g_wk  + (size_t)off*4; }
            else if (reg == 2) { src = Wv + off; dst = g_wvw + (size_t)off*4; }
            else               { src = Wp + off; dst = g_wp  + (size_t)off*4; }
        }
        float4 a = *src;
        __half2* d2 = (__half2*)dst;
        d2[0] = __floats2half2_rn(a.x * s, a.y * s);
        d2[1] = __floats2half2_rn(a.z * s, a.w * s);
    } else {
        int idx = i - (NX4 + 4*NW4);
        int c4 = idx % (C_/4);
        int bm = idx / (C_/4);
        int m  = bm % M_;
        int b  = bm / M_;
        float4 kk = xl[((size_t)(b*M_ + m)*2 + 0)*(C_/4) + c4];
        float4 vv = xl[((size_t)(b*M_ + m)*2 + 1)*(C_/4) + c4];
        __half2* kp = (__half2*)(g_k + (size_t)(b*TK_ + m)*C_ + c4*4);
        __half2* vp = (__half2*)(g_v + (size_t)(b*TK_ + m)*C_ + c4*4);
        kp[0] = __floats2half2_rn(kk.x, kk.y); kp[1] = __floats2half2_rn(kk.z, kk.w);
        vp[0] = __floats2half2_rn(vv.x, vv.y); vp[1] = __floats2half2_rn(vv.z, vv.w);
    }
}

// ---------------- projection GEMMs (fp16, 128x128, k-chunk 64) --------------
#define PLDA 72    // halves (64 + 8 pad)
#define PLDB 136   // halves
#define PLDC 136   // floats
#define PROJ_SMEM_BYTES ((2*128*PLDA + 2*64*PLDB)*2)   // 71680; Cs (69632) aliases

struct ProjAcc {
    wmma::fragment<wmma::accumulator,16,16,16,float> acc[2][4];
};

__device__ __forceinline__ void proj_issue(__half* As, __half* Bs, int buf,
                                           const __half* A, const __half* W,
                                           int row0, int wcol0, int kc, int tid) {
    #pragma unroll
    for (int ch = tid; ch < 1024; ch += 256) {
        int r = ch >> 3, s = ch & 7;   // 128 rows x 8 chunks (64 halves)
        cp16(&As[(size_t)buf*128*PLDA + r*PLDA + s*8], A + (size_t)(row0 + r)*C_ + kc*64 + s*8);
    }
    #pragma unroll
    for (int ch = tid; ch < 1024; ch += 256) {
        int r = ch >> 4, s = ch & 15;  // 64 rows x 16 chunks (128 halves)
        cp16(&Bs[(size_t)buf*64*PLDB + r*PLDB + s*8], W + (size_t)(kc*64 + r)*C_ + wcol0 + s*8);
    }
    CP_COMMIT();
}

__device__ __forceinline__ void proj_mainloop(float* sm, const __half* A, const __half* W,
                                              int row0, int wcol0, ProjAcc& P) {
    __half* As = (__half*)sm;
    __half* Bs = (__half*)sm + 2*128*PLDA;
    int tid = threadIdx.x, warp = tid >> 5;
    int wr = warp >> 1, wc = warp & 1;

    #pragma unroll
    for (int i = 0; i < 2; i++)
        #pragma unroll
        for (int j = 0; j < 4; j++) wmma::fill_fragment(P.acc[i][j], 0.0f);

    proj_issue(As, Bs, 0, A, W, row0, wcol0, 0, tid);
    for (int kc = 0; kc < 16; kc++) {
        int buf = kc & 1;
        CP_WAIT0();
        __syncthreads();
        if (kc + 1 < 16) proj_issue(As, Bs, buf ^ 1, A, W, row0, wcol0, kc + 1, tid);
        __half* Ab = &As[(size_t)buf*128*PLDA];
        __half* Bb = &Bs[(size_t)buf*64*PLDB];
        #pragma unroll
        for (int ks = 0; ks < 4; ks++) {
            wmma::fragment<wmma::matrix_a,16,16,16,__half,wmma::row_major> a0, a1;
            wmma::load_matrix_sync(a0, &Ab[(wr*32     )*PLDA + ks*16], PLDA);
            wmma::load_matrix_sync(a1, &Ab[(wr*32 + 16)*PLDA + ks*16], PLDA);
            #pragma unroll
            for (int j = 0; j < 4; j++) {
                wmma::fragment<wmma::matrix_b,16,16,16,__half,wmma::row_major> b;
                wmma::load_matrix_sync(b, &Bb[(ks*16)*PLDB + wc*64 + j*16], PLDB);
                wmma::mma_sync(P.acc[0][j], a0, b, P.acc[0][j]);
                wmma::mma_sync(P.acc[1][j], a1, b, P.acc[1][j]);
            }
        }
    }
    __syncthreads();
    float* Cs = sm;
    #pragma unroll
    for (int i = 0; i < 2; i++)
        #pragma unroll
        for (int j = 0; j < 4; j++)
            wmma::store_matrix_sync(&Cs[(wr*32 + i*16)*PLDC + wc*64 + j*16],
                                    P.acc[i][j], PLDC, wmma::mem_row_major);
    __syncthreads();
}

__global__ __launch_bounds__(256, 2) void proj_qkv_kernel(float* __restrict__ out_xl) {
    extern __shared__ __align__(16) float sm[];
    int col0 = blockIdx.x * 128;
    int row0 = blockIdx.y * 128;
    int wsel  = col0 >> 10;
    int wcol0 = col0 & 1023;
    const __half* W = (wsel == 0) ? g_wq : ((wsel == 1) ? g_wk : g_wvw);

    ProjAcc P;
    proj_mainloop(sm, g_xh, W, row0, wcol0, P);

    float* Cs = sm;
    int tid = threadIdx.x;
    for (int i = tid; i < 128*64; i += 256) {
        int r = i >> 6, c2 = (i & 63) * 2;
        float v0 = Cs[r*PLDC + c2];
        float v1 = Cs[r*PLDC + c2 + 1];
        int row = row0 + r;
        int b = row >> 11, t = row & 2047;
        int cc = wcol0 + c2;
        __half2 hv = __floats2half2_rn(v0, v1);
        if (wsel == 0) {
            *(__half2*)(g_q + (size_t)row*C_ + cc) = hv;
        } else if (wsel == 1) {
            *(__half2*)(g_k + ((size_t)b*TK_ + M_ + t)*C_ + cc) = hv;
            *(float2*)(out_xl + (((size_t)(b*T_ + t))*2 + 0)*C_ + cc) = make_float2(v0, v1);
        } else {
            *(__half2*)(g_v + ((size_t)b*TK_ + M_ + t)*C_ + cc) = hv;
            *(float2*)(out_xl + (((size_t)(b*T_ + t))*2 + 1)*C_ + cc) = make_float2(v0, v1);
        }
    }
}

__global__ __launch_bounds__(256, 2) void proj_out_kernel(const float* __restrict__ bp,
                                                          float* __restrict__ out) {
    extern __shared__ __align__(16) float sm[];
    int col0 = blockIdx.x * 128;
    int row0 = blockIdx.y * 128;

    ProjAcc P;
    proj_mainloop(sm, g_wv, g_wp, row0, col0, P);

    float* Cs = sm;
    int tid = threadIdx.x;
    for (int i = tid; i < 128*64; i += 256) {
        int r = i >> 6, c2 = (i & 63) * 2;
        float2 v = make_float2(Cs[r*PLDC + c2]     + bp[col0 + c2],
                               Cs[r*PLDC + c2 + 1] + bp[col0 + c2 + 1]);
        *(float2*)(out + (size_t)(row0 + r)*C_ + col0 + c2) = v;
    }
}

// ---------------- flash attention (R13 verbatim: 3-stage ring) ---------------
#define LDH 72
#define AK_OFF (128*LDH)
#define AV_OFF (AK_OFF + 3*64*LDH)
#define ATTN_SMEM_BYTES ((128*LDH + 6*64*LDH)*2)   // 73728; x2 CTAs = 147456

#define MMA_F16(C0,C1,C2,C3,A0,A1,A2,A3,Bb0,Bb1)                               \
    asm volatile("mma.sync.aligned.m16n8k16.row.col.f32.f16.f16.f32 "          \
                 "{%0,%1,%2,%3},{%4,%5,%6,%7},{%8,%9},{%0,%1,%2,%3};"          \
                 : "+f"(C0), "+f"(C1), "+f"(C2), "+f"(C3)                      \
                 : "r"(A0), "r"(A1), "r"(A2), "r"(A3), "r"(Bb0), "r"(Bb1))

__global__ __launch_bounds__(128, 2) void attn_kernel(const float* __restrict__ rel) {
    extern __shared__ __align__(16) __half smh[];
    __half* Qs = smh;
    __half* Ks = smh + AK_OFF;
    __half* Vs = smh + AV_OFF;

    int bx = blockIdx.x;
    int b  = bx & 1;
    int qt = 15 - (bx >> 1);
    int h  = blockIdx.y;
    int qi0 = qt * 128;
    int tid = threadIdx.x, warp = tid >> 5, lane = tid & 31;
    int g  = lane >> 2;
    int t4 = lane & 3;

    const __half* kbase = g_k + (size_t)b*TK_*C_ + h*64;
    const __half* vbase = g_v + (size_t)b*TK_*C_ + h*64;
    const __half* qbase = g_q + ((size_t)b*T_ + qi0)*C_ + h*64;
    const float*  relb  = rel + (size_t)h*T_*TK_;

    int ntiles = 2*qt + 34;

    for (int ch = tid; ch < 1024; ch += 128) {
        int r = ch >> 3, s = ch & 7;
        cp16(&Qs[r*LDH + s*8], qbase + (size_t)r*C_ + s*8);
    }
    CP_COMMIT();
    #pragma unroll
    for (int pre = 0; pre < 2; pre++) {
        for (int ch = tid; ch < 1024; ch += 128) {
            if (ch < 512) {
                int r = ch >> 3, s = ch & 7;
                cp16(&Ks[pre*64*LDH + r*LDH + s*8], kbase + (size_t)(pre*64 + r)*C_ + s*8);
            } else {
                int c2 = ch - 512;
                int r = c2 >> 3, s = c2 & 7;
                cp16(&Vs[pre*64*LDH + r*LDH + s*8], vbase + (size_t)(pre*64 + r)*C_ + s*8);
            }
        }
        CP_COMMIT();
    }

    // V padding cols 64..71 (ones column at 64) for all 3 ring buffers
    for (int i = tid; i < 3*64; i += 128) {
        __half2* pad = (__half2*)(Vs + (size_t)i*LDH + 64);
        pad[0] = __floats2half2_rn(1.0f, 0.0f);
        pad[1] = __floats2half2_rn(0.0f, 0.0f);
        pad[2] = __floats2half2_rn(0.0f, 0.0f);
        pad[3] = __floats2half2_rn(0.0f, 0.0f);
    }

    CP_WAIT2();
    __syncthreads();

    int lm   = lane & 15;
    int lmc  = (lane >> 4) * 8;
    int lmrt = ((lane >> 3) & 1) * 8 + (lane & 7);
    int lmct = (lane >> 4) * 8;
    unsigned qsm  = (unsigned)__cvta_generic_to_shared(Qs);
    unsigned ksm0 = (unsigned)__cvta_generic_to_shared(Ks);
    unsigned vsm0 = (unsigned)__cvta_generic_to_shared(Vs);

    unsigned qa[2][4][4];
    #pragma unroll
    for (int s = 0; s < 2; s++)
        #pragma unroll
        for (int kk = 0; kk < 4; kk++) {
            unsigned addr = qsm + (unsigned)(((warp*32 + s*16 + lm)*LDH + kk*16 + lmc) * 2);
            asm volatile("ldmatrix.sync.aligned.m8n8.x4.shared.b16 {%0,%1,%2,%3}, [%4];"
                         : "=r"(qa[s][kk][0]), "=r"(qa[s][kk][1]),
                           "=r"(qa[s][kk][2]), "=r"(qa[s][kk][3])
                         : "r"(addr));
        }

    float o[2][8][4];
    float oE[2][4];
    #pragma unroll
    for (int s = 0; s < 2; s++) {
        #pragma unroll
        for (int n = 0; n < 8; n++)
            #pragma unroll
            for (int j = 0; j < 4; j++) o[s][n][j] = 0.0f;
        #pragma unroll
        for (int j = 0; j < 4; j++) oE[s][j] = 0.0f;
    }

    for (int kt = 0; kt < ntiles; kt++) {
        int buf = kt % 3;
        int kj0 = kt * 64;

        // strip-0 bias prefetch (overlaps pipeline wait + QK)
        int row0s = qi0 + warp*32 + g;
        float2 rv0[16];
        {
            const float2* rl = (const float2*)(relb + (size_t)row0s*TK_ + kj0);
            const float2* rh = (const float2*)(relb + (size_t)(row0s + 8)*TK_ + kj0);
            #pragma unroll
            for (int n = 0; n < 8; n++) {
                rv0[n]     = __ldg(rl + 4*n + t4);
                rv0[8 + n] = __ldg(rh + 4*n + t4);
            }
        }

        CP_WAIT1();
        __syncthreads();
        if (kt + 2 < ntiles) {
            int tt = kt + 2, nb = tt % 3;
            for (int ch = tid; ch < 1024; ch += 128) {
                if (ch < 512) {
                    int r = ch >> 3, s = ch & 7;
                    cp16(&Ks[nb*64*LDH + r*LDH + s*8], kbase + (size_t)(tt*64 + r)*C_ + s*8);
                } else {
                    int c2 = ch - 512;
                    int r = c2 >> 3, s = c2 & 7;
                    cp16(&Vs[nb*64*LDH + r*LDH + s*8], vbase + (size_t)(tt*64 + r)*C_ + s*8);
                }
            }
            CP_COMMIT();
        }
        unsigned ksm = ksm0 + (unsigned)(buf * 64 * LDH * 2);
        unsigned vsm = vsm0 + (unsigned)(buf * 64 * LDH * 2);

        // ---- S = Q @ K^T, both strips, K frags read once per warp ----
        float accS[2][8][4];
        #pragma unroll
        for (int s = 0; s < 2; s++)
            #pragma unroll
            for (int n = 0; n < 8; n++)
                #pragma unroll
                for (int j = 0; j < 4; j++) accS[s][n][j] = 0.0f;
        #pragma unroll
        for (int kk = 0; kk < 4; kk++) {
            #pragma unroll
            for (int np = 0; np < 4; np++) {
                unsigned addr = ksm + (unsigned)(((16*np + lm)*LDH + kk*16 + lmc) * 2);
                unsigned r0, r1, r2, r3;
                asm volatile("ldmatrix.sync.aligned.m8n8.x4.shared.b16 {%0,%1,%2,%3}, [%4];"
                             : "=r"(r0), "=r"(r1), "=r"(r2), "=r"(r3) : "r"(addr));
                #pragma unroll
                for (int s = 0; s < 2; s++) {
                    MMA_F16(accS[s][2*np][0], accS[s][2*np][1], accS[s][2*np][2], accS[s][2*np][3],
                            qa[s][kk][0], qa[s][kk][1], qa[s][kk][2], qa[s][kk][3], r0, r2);
                    MMA_F16(accS[s][2*np+1][0], accS[s][2*np+1][1], accS[s][2*np+1][2], accS[s][2*np+1][3],
                            qa[s][kk][0], qa[s][kk][1], qa[s][kk][2], qa[s][kk][3], r1, r3);
                }
            }
        }

        // strip-1 bias (prefetched before softmax, overlapping)
        float2 rv1[16];
        {
            int row1s = row0s + 16;
            const float2* rl = (const float2*)(relb + (size_t)row1s*TK_ + kj0);
            const float2* rh = (const float2*)(relb + (size_t)(row1s + 8)*TK_ + kj0);
            #pragma unroll
            for (int n = 0; n < 8; n++) {
                rv1[n]     = __ldg(rl + 4*n + t4);
                rv1[8 + n] = __ldg(rh + 4*n + t4);
            }
        }

        bool masked = (kt >= ntiles - 2);

        // ---- softmax both strips: fp32 logit -> f16x2 pack -> ex2.f16x2 ----
        unsigned pg[2][8], ph[2][8];
        #pragma unroll
        for (int s = 0; s < 2; s++) {
            float2* rv = (s == 0) ? rv0 : rv1;
            int rowbase = row0s + s*16;
            int lim_lo = rowbase + 2048 - kj0;
            int lim_hi = lim_lo + 8;
            #pragma unroll
            for (int n = 0; n < 8; n++) {
                int cbase = 8*n + 2*t4;
                float p0 = fmaf(rv[n].x,     CSL, accS[s][n][0]);
                float p1 = fmaf(rv[n].y,     CSL, accS[s][n][1]);
                float q0 = fmaf(rv[8 + n].x, CSL, accS[s][n][2]);
                float q1 = fmaf(rv[8 + n].y, CSL, accS[s][n][3]);
                if (masked) {
                    if (cbase     > lim_lo) p0 = -100000.0f;
                    if (cbase + 1 > lim_lo) p1 = -100000.0f;
                    if (cbase     > lim_hi) q0 = -100000.0f;
                    if (cbase + 1 > lim_hi) q1 = -100000.0f;
                }
                unsigned u0, u1;
                asm("cvt.rn.f16x2.f32 %0, %1, %2;" : "=r"(u0) : "f"(p1), "f"(p0));
                asm("ex2.approx.f16x2 %0, %1;"     : "=r"(pg[s][n]) : "r"(u0));
                asm("cvt.rn.f16x2.f32 %0, %1, %2;" : "=r"(u1) : "f"(q1), "f"(q0));
                asm("ex2.approx.f16x2 %0, %1;"     : "=r"(ph[s][n]) : "r"(u1));
            }
        }

        // ---- PV: one V-fragment load serves both strips; ones-col -> sums ----
        #pragma unroll
        for (int kk = 0; kk < 4; kk++) {
            unsigned a00 = pg[0][2*kk], a01 = ph[0][2*kk];
            unsigned a02 = pg[0][2*kk+1], a03 = ph[0][2*kk+1];
            unsigned a10 = pg[1][2*kk], a11 = ph[1][2*kk];
            unsigned a12 = pg[1][2*kk+1], a13 = ph[1][2*kk+1];
            #pragma unroll
            for (int jv = 0; jv < 4; jv++) {
                unsigned baddr = vsm + (unsigned)(((16*kk + lmrt)*LDH + 16*jv + lmct) * 2);
                unsigned b0, b1, b2, b3;
                asm volatile("ldmatrix.sync.aligned.m8n8.x4.trans.shared.b16 "
                             "{%0,%1,%2,%3}, [%4];"
                             : "=r"(b0), "=r"(b1), "=r"(b2), "=r"(b3) : "r"(baddr));
                MMA_F16(o[0][2*jv][0], o[0][2*jv][1], o[0][2*jv][2], o[0][2*jv][3],
                        a00, a01, a02, a03, b0, b1);
                MMA_F16(o[0][2*jv+1][0], o[0][2*jv+1][1], o[0][2*jv+1][2], o[0][2*jv+1][3],
                        a00, a01, a02, a03, b2, b3);
                MMA_F16(o[1][2*jv][0], o[1][2*jv][1], o[1][2*jv][2], o[1][2*jv][3],
                        a10, a11, a12, a13, b0, b1);
                MMA_F16(o[1][2*jv+1][0], o[1][2*jv+1][1], o[1][2*jv+1][2], o[1][2*jv+1][3],
                        a10, a11, a12, a13, b2, b3);
            }
            unsigned caddr = vsm + (unsigned)(((16*kk + (lane & 15))*LDH + 64) * 2);
            unsigned c0, c1;
            asm volatile("ldmatrix.sync.aligned.m8n8.x2.trans.shared.b16 {%0,%1}, [%2];"
                         : "=r"(c0), "=r"(c1) : "r"(caddr));
            MMA_F16(oE[0][0], oE[0][1], oE[0][2], oE[0][3], a00, a01, a02, a03, c0, c1);
            MMA_F16(oE[1][0], oE[1][1], oE[1][2], oE[1][3], a10, a11, a12, a13, c0, c1);
        }
    }

    // ---- normalize + write ----
    #pragma unroll
    for (int s = 0; s < 2; s++) {
        float sum_lo = __shfl_sync(0xFFFFFFFFu, oE[s][0], lane & 28);
        float sum_hi = __shfl_sync(0xFFFFFFFFu, oE[s][2], lane & 28);
        float inv_lo = 1.0f / sum_lo;
        float inv_hi = 1.0f / sum_hi;
        int rowbase = warp*32 + s*16 + g;
        __half* wv_lo = g_wv + ((size_t)b*T_ + qi0 + rowbase    )*C_ + h*64 + 2*t4;
        __half* wv_hi = g_wv + ((size_t)b*T_ + qi0 + rowbase + 8)*C_ + h*64 + 2*t4;
        #pragma unroll
        for (int n = 0; n < 8; n++) {
            *(__half2*)(wv_lo + 8*n) = __floats2half2_rn(o[s][n][0]*inv_lo, o[s][n][1]*inv_lo);
            *(__half2*)(wv_hi + 8*n) = __floats2half2_rn(o[s][n][2]*inv_hi, o[s][n][3]*inv_hi);
        }
    }
}

// ---------------- launch ----------------------------------------------------
extern "C" void kernel_launch(void* const* d_in, const int* in_sizes, int n_in,
                              void* d_out, int out_size) {
    const float* rel = (const float*)d_in[0];
    const float* x   = (const float*)d_in[1];
    const float* xl  = (const float*)d_in[2];
    const float* Wq  = (const float*)d_in[3];
    const float* Wk  = (const float*)d_in[4];
    const float* Wv  = (const float*)d_in[5];
    const float* Wp  = (const float*)d_in[6];
    const float* bp  = (const float*)d_in[7];

    float* out    = (float*)d_out;
    float* out_xl = out + (size_t)B_*T_*C_;

    cudaFuncSetAttribute(proj_qkv_kernel, cudaFuncAttributeMaxDynamicSharedMemorySize, PROJ_SMEM_BYTES);
    cudaFuncSetAttribute(proj_out_kernel, cudaFuncAttributeMaxDynamicSharedMemorySize, PROJ_SMEM_BYTES);
    cudaFuncSetAttribute(attn_kernel,     cudaFuncAttributeMaxDynamicSharedMemorySize, ATTN_SMEM_BYTES);

    prep_kernel<<<(NPREP + 255)/256, 256>>>((const float4*)x,  (const float4*)Wq,
                                            (const float4*)Wk, (const float4*)Wv,
                                            (const float4*)Wp, (const float4*)xl);

    proj_qkv_kernel<<<dim3(24, 32), 256, PROJ_SMEM_BYTES>>>(out_xl);
    attn_kernel<<<dim3(32, 16), 128, ATTN_SMEM_BYTES>>>(rel);
    proj_out_kernel<<<dim3(8, 32), 256, PROJ_SMEM_BYTES>>>(bp, out);
}